// round 1
// baseline (speedup 1.0000x reference)
#include <cuda_runtime.h>
#include <cuda_bf16.h>
#include <cstdint>

// Problem constants (fixed by the dataset)
#define NN    20000
#define EE    320000
#define DD    128
#define HD    256          // H*D
#define NJQKV 1792         // 7 * 256 output cols of fused projection
#define SCALE 16.0f        // sqrt(D*H) = sqrt(256)

// ---------------- scratch (device globals; no allocation) ----------------
__device__ float g_qkv[(size_t)NN * NJQKV];   // [N, 1792]: [0,256)=Q, [256,1024)=K(rel), [1024,1792)=V(rel)
__device__ float g_z[(size_t)NN * HD];        // [N, 256] aggregated weighted V
__device__ float g_numer[(size_t)EE * 2];     // [E, H]
__device__ float g_denom[(size_t)NN * 2];     // [N, H]
__device__ int   g_deg[NN];
__device__ int   g_rowptr[NN + 1];
__device__ int   g_cursor[NN];
__device__ int   g_eid[EE];                   // edge ids sorted by dst (CSR)

// ---------------- init ----------------
__global__ void k_init(int n)
{
    int i = blockIdx.x * blockDim.x + threadIdx.x;
    if (i < 2 * n) g_denom[i] = 0.0f;
    if (i < n) { g_deg[i] = 0; g_cursor[i] = 0; }
}

// ---------------- fused projection / output GEMM ----------------
// C[m, j] = sum_d A[m, d] * W(j, d), KDIM = inner dim.
// Weight segments: j in [0,256) -> W0, [256,1024) -> W1, [1024,1792) -> W2.
// BN=64 tiles never straddle segment boundaries.
template <int KDIM>
__global__ __launch_bounds__(256)
void sgemm_kernel(const float* __restrict__ A,
                  const float* __restrict__ W0,
                  const float* __restrict__ W1,
                  const float* __restrict__ W2,
                  float* __restrict__ C,
                  int M, int ldc)
{
    constexpr int BM = 64, BN = 64, BK = 32;
    __shared__ float As[BM][BK + 1];
    __shared__ float Bs[BN][BK + 1];

    const int tid = threadIdx.x;
    const int tx = tid & 15;        // 0..15 -> 4 output cols each
    const int ty = tid >> 4;        // 0..15 -> 4 output rows each
    const int m0 = blockIdx.y * BM;
    const int j0 = blockIdx.x * BN;

    const float* wbase;
    if (j0 < 256)        wbase = W0 + (size_t)j0 * KDIM;
    else if (j0 < 1024)  wbase = W1 + (size_t)(j0 - 256) * KDIM;
    else                 wbase = W2 + (size_t)(j0 - 1024) * KDIM;

    float c[4][4] = {};

    for (int kt = 0; kt < KDIM; kt += BK) {
        // cooperative loads: 64x32 each, 8 elems/thread, coalesced along k
        #pragma unroll
        for (int p = 0; p < 8; p++) {
            int elem = p * 256 + tid;
            int mm = elem >> 5;
            int kk = elem & 31;
            int gm = m0 + mm;
            As[mm][kk] = (gm < M) ? A[(size_t)gm * KDIM + kt + kk] : 0.0f;
            Bs[mm][kk] = wbase[(size_t)mm * KDIM + kt + kk];
        }
        __syncthreads();

        #pragma unroll
        for (int kk = 0; kk < BK; kk++) {
            float a[4], b[4];
            #pragma unroll
            for (int i = 0; i < 4; i++) a[i] = As[ty * 4 + i][kk];
            #pragma unroll
            for (int j = 0; j < 4; j++) b[j] = Bs[tx * 4 + j][kk];
            #pragma unroll
            for (int i = 0; i < 4; i++)
                #pragma unroll
                for (int j = 0; j < 4; j++)
                    c[i][j] += a[i] * b[j];
        }
        __syncthreads();
    }

    #pragma unroll
    for (int i = 0; i < 4; i++) {
        int gm = m0 + ty * 4 + i;
        if (gm < M) {
            #pragma unroll
            for (int j = 0; j < 4; j++)
                C[(size_t)gm * ldc + j0 + tx * 4 + j] = c[i][j];
        }
    }
}

// ---------------- edge pass A: scores -> numer, denom atomics, deg histogram ----------------
// one warp per edge; 256 elems: lane covers [lane*8, lane*8+8); lanes 0-15 = head0, 16-31 = head1
__global__ __launch_bounds__(256)
void k_edgeA(const int* __restrict__ esrc, const int* __restrict__ edst,
             const int* __restrict__ erel, int E)
{
    int warp = (blockIdx.x * blockDim.x + threadIdx.x) >> 5;
    int lane = threadIdx.x & 31;
    if (warp >= E) return;

    int src = esrc[warp];
    int dst = edst[warp];
    int rel = erel[warp];

    const float4* qp = (const float4*)(g_qkv + (size_t)dst * NJQKV + lane * 8);
    const float4* kp = (const float4*)(g_qkv + (size_t)src * NJQKV + 256 + rel * 256 + lane * 8);
    float4 qa = qp[0], qb = qp[1];
    float4 ka = kp[0], kb = kp[1];

    float p = qa.x * ka.x + qa.y * ka.y + qa.z * ka.z + qa.w * ka.w
            + qb.x * kb.x + qb.y * kb.y + qb.z * kb.z + qb.w * kb.w;

    // reduce within each 16-lane half (head)
    #pragma unroll
    for (int off = 8; off >= 1; off >>= 1)
        p += __shfl_xor_sync(0xffffffffu, p, off);

    if (lane == 0 || lane == 16) {
        int h = lane >> 4;
        float s = p / SCALE;
        float nu = fmaxf(s, 0.0f);
        nu = nu * nu + 1e-10f;
        g_numer[2 * warp + h] = nu;
        atomicAdd(&g_denom[2 * dst + h], nu);
    }
    if (lane == 0) atomicAdd(&g_deg[dst], 1);
}

// ---------------- exclusive scan -> rowptr (single block) ----------------
__global__ void k_scan(int n)
{
    __shared__ int sh[1024];
    __shared__ int carry;
    if (threadIdx.x == 0) { carry = 0; g_rowptr[0] = 0; }
    __syncthreads();

    for (int base = 0; base < n; base += 1024) {
        int i = base + (int)threadIdx.x;
        int v = (i < n) ? g_deg[i] : 0;
        sh[threadIdx.x] = v;
        __syncthreads();
        for (int off = 1; off < 1024; off <<= 1) {
            int t = (threadIdx.x >= (unsigned)off) ? sh[threadIdx.x - off] : 0;
            __syncthreads();
            sh[threadIdx.x] += t;
            __syncthreads();
        }
        int incl = sh[threadIdx.x] + carry;
        if (i < n) g_rowptr[i + 1] = incl;
        __syncthreads();
        if (threadIdx.x == 1023) carry = incl;
        __syncthreads();
    }
}

// ---------------- scatter edges into CSR ----------------
__global__ void k_scatter(const int* __restrict__ edst, int E)
{
    int e = blockIdx.x * blockDim.x + threadIdx.x;
    if (e >= E) return;
    int dst = edst[e];
    int pos = atomicAdd(&g_cursor[dst], 1);
    g_eid[g_rowptr[dst] + pos] = e;
}

// ---------------- pull pass: z[n] = sum_{e in mailbox(n)} w_e * v_e ----------------
// one warp per dst node; lane covers 8 consecutive elems of the 256-wide row
__global__ __launch_bounds__(256)
void k_pull(const int* __restrict__ esrc, const int* __restrict__ erel, int N)
{
    int warp = (blockIdx.x * blockDim.x + threadIdx.x) >> 5;
    int lane = threadIdx.x & 31;
    if (warp >= N) return;

    float den0 = g_denom[2 * warp];
    float den1 = g_denom[2 * warp + 1];
    float inv = (lane < 16) ? (den0 > 0.0f ? 1.0f / den0 : 0.0f)
                            : (den1 > 0.0f ? 1.0f / den1 : 0.0f);
    int h = lane >> 4;

    float4 acc0 = {0, 0, 0, 0}, acc1 = {0, 0, 0, 0};

    int start = g_rowptr[warp];
    int end   = g_rowptr[warp + 1];
    for (int j = start; j < end; j++) {
        int e   = g_eid[j];
        int src = esrc[e];
        int rel = erel[e];
        float w = g_numer[2 * e + h] * inv;
        const float4* vp = (const float4*)(g_qkv + (size_t)src * NJQKV + 1024 + rel * 256 + lane * 8);
        float4 v0 = vp[0], v1 = vp[1];
        acc0.x += w * v0.x; acc0.y += w * v0.y; acc0.z += w * v0.z; acc0.w += w * v0.w;
        acc1.x += w * v1.x; acc1.y += w * v1.y; acc1.z += w * v1.z; acc1.w += w * v1.w;
    }

    float4* zp = (float4*)(g_z + (size_t)warp * HD + lane * 8);
    zp[0] = acc0;
    zp[1] = acc1;
}

// ---------------- launch ----------------
extern "C" void kernel_launch(void* const* d_in, const int* in_sizes, int n_in,
                              void* d_out, int out_size)
{
    const float* X   = (const float*)d_in[0];   // [N,128]
    const float* WQ  = (const float*)d_in[1];   // [256,128]
    const float* WK  = (const float*)d_in[2];   // [3,256,128]
    const float* WV  = (const float*)d_in[3];   // [3,256,128]
    const float* WO  = (const float*)d_in[4];   // [128,256]
    const int*  esrc = (const int*)d_in[5];     // [E]
    const int*  edst = (const int*)d_in[6];     // [E]
    const int*  erel = (const int*)d_in[7];     // [E]
    float* out = (float*)d_out;

    const int N = in_sizes[0] / DD;   // 20000
    const int E = in_sizes[5];        // 320000

    float* qkv; cudaGetSymbolAddress((void**)&qkv, g_qkv);
    float* z;   cudaGetSymbolAddress((void**)&z,   g_z);

    // 1. init
    k_init<<<(2 * N + 255) / 256, 256>>>(N);

    // 2. fused projection GEMM: [N,128] x [1792,128]^T -> g_qkv [N,1792]
    {
        dim3 grid(NJQKV / 64, (N + 63) / 64);
        sgemm_kernel<DD><<<grid, 256>>>(X, WQ, WK, WV, qkv, N, NJQKV);
    }

    // 3. edge scores + denom + degree histogram
    k_edgeA<<<(E + 7) / 8, 256>>>(esrc, edst, erel, E);

    // 4. scan degrees -> rowptr
    k_scan<<<1, 1024>>>(N);

    // 5. scatter edge ids into CSR
    k_scatter<<<(E + 255) / 256, 256>>>(edst, E);

    // 6. pull-based weighted V aggregation -> g_z [N,256]
    k_pull<<<(N + 7) / 8, 256>>>(esrc, erel, N);

    // 7. output GEMM: [N,256] x [128,256]^T -> out [N,128]
    {
        dim3 grid(DD / 64, (N + 63) / 64);
        sgemm_kernel<HD><<<grid, 256>>>(z, WO, WO, WO, out, N, DD);
    }
}

// round 3
// speedup vs baseline: 1.3764x; 1.3764x over previous
#include <cuda_runtime.h>
#include <cuda_bf16.h>
#include <cstdint>

// Problem constants (fixed by the dataset)
#define NN    20000
#define MPAD  20096        // 157 * 128
#define EE    320000
#define DD    128
#define HD    256          // H*D
#define NJQKV 1792         // 7 * 256 output cols of fused projection
#define SCALE 16.0f        // sqrt(D*H)

// ---------------- scratch (device globals; no allocation) ----------------
__device__ float          g_qkv[(size_t)NN * NJQKV];  // fp32 [N,1792]: Q | K(r0..2) | V(r0..2)
__device__ __nv_bfloat16  g_xh[(size_t)MPAD * DD];
__device__ __nv_bfloat16  g_xl[(size_t)MPAD * DD];
__device__ __nv_bfloat16  g_wh[(size_t)NJQKV * DD];
__device__ __nv_bfloat16  g_wl[(size_t)NJQKV * DD];
__device__ __nv_bfloat16  g_woh[(size_t)DD * HD];
__device__ __nv_bfloat16  g_wol[(size_t)DD * HD];
__device__ __nv_bfloat16  g_zh[(size_t)MPAD * HD];
__device__ __nv_bfloat16  g_zl[(size_t)MPAD * HD];
__device__ float g_numer[(size_t)EE * 2];
__device__ int   g_deg[NN];
__device__ int   g_rowptr[NN + 1];
__device__ int   g_cursor[NN];
__device__ int   g_eid[EE];

__device__ __forceinline__ uint32_t smem_u32(const void* p) {
    uint32_t a;
    asm("{ .reg .u64 t; cvta.to.shared.u64 t, %1; cvt.u32.u64 %0, t; }" : "=r"(a) : "l"(p));
    return a;
}

__device__ __forceinline__ void ldsm_x4(uint32_t& r0, uint32_t& r1, uint32_t& r2, uint32_t& r3,
                                        uint32_t addr) {
    asm volatile("ldmatrix.sync.aligned.m8n8.x4.shared.b16 {%0,%1,%2,%3}, [%4];"
                 : "=r"(r0), "=r"(r1), "=r"(r2), "=r"(r3) : "r"(addr));
}

__device__ __forceinline__ void mma_bf16(float* d, const uint32_t* a, const uint32_t* b) {
    asm volatile(
        "mma.sync.aligned.m16n8k16.row.col.f32.bf16.bf16.f32 "
        "{%0,%1,%2,%3}, {%4,%5,%6,%7}, {%8,%9}, {%0,%1,%2,%3};"
        : "+f"(d[0]), "+f"(d[1]), "+f"(d[2]), "+f"(d[3])
        : "r"(a[0]), "r"(a[1]), "r"(a[2]), "r"(a[3]), "r"(b[0]), "r"(b[1]));
}

// ---------------- init ----------------
__global__ void k_init()
{
    int i = blockIdx.x * blockDim.x + threadIdx.x;
    if (i < NN) { g_deg[i] = 0; g_cursor[i] = 0; }
    int padn = (MPAD - NN) * HD;   // 24576
    if (i < padn) {
        g_zh[(size_t)NN * HD + i] = __float2bfloat16(0.0f);
        g_zl[(size_t)NN * HD + i] = __float2bfloat16(0.0f);
    }
}

// ---------------- fp32 -> bf16 hi/lo split ----------------
__global__ void k_split(const float* __restrict__ s, __nv_bfloat16* __restrict__ h,
                        __nv_bfloat16* __restrict__ l, int nreal, int ntot)
{
    int i = blockIdx.x * blockDim.x + threadIdx.x;
    if (i >= ntot) return;
    float x = (i < nreal) ? s[i] : 0.0f;
    __nv_bfloat16 hi = __float2bfloat16(x);
    float lo = x - __bfloat162float(hi);
    h[i] = hi;
    l[i] = __float2bfloat16(lo);
}

// ---------------- degree histogram ----------------
__global__ void k_deg(const int* __restrict__ edst, int E)
{
    int e = blockIdx.x * blockDim.x + threadIdx.x;
    if (e < E) atomicAdd(&g_deg[edst[e]], 1);
}

// ---------------- fast scan (1 block, 1024 thr, 20 elems/thread) ----------------
__global__ __launch_bounds__(1024) void k_scan(int n)
{
    const int P = 20;
    __shared__ int wsum[32];
    int tid = threadIdx.x, lane = tid & 31, wid = tid >> 5;
    int base = tid * P;
    int v[P];
    int s = 0;
    #pragma unroll
    for (int i = 0; i < P; i++) {
        int idx = base + i;
        int d = (idx < n) ? g_deg[idx] : 0;
        s += d;
        v[i] = s;
    }
    int x = s;
    #pragma unroll
    for (int off = 1; off < 32; off <<= 1) {
        int t = __shfl_up_sync(0xffffffffu, x, off);
        if (lane >= off) x += t;
    }
    if (lane == 31) wsum[wid] = x;
    __syncthreads();
    if (wid == 0) {
        int y = wsum[lane];
        #pragma unroll
        for (int off = 1; off < 32; off <<= 1) {
            int t = __shfl_up_sync(0xffffffffu, y, off);
            if (lane >= off) y += t;
        }
        wsum[lane] = y;
    }
    __syncthreads();
    int offset = (wid ? wsum[wid - 1] : 0) + x - s;
    if (tid == 0) g_rowptr[0] = 0;
    #pragma unroll
    for (int i = 0; i < P; i++) {
        int idx = base + i;
        if (idx < n) g_rowptr[idx + 1] = offset + v[i];
    }
}

// ---------------- scatter edges into CSR ----------------
__global__ void k_scatter(const int* __restrict__ edst, int E)
{
    int e = blockIdx.x * blockDim.x + threadIdx.x;
    if (e >= E) return;
    int dst = edst[e];
    int pos = atomicAdd(&g_cursor[dst], 1);
    g_eid[g_rowptr[dst] + pos] = e;
}

// ---------------- mma.sync GEMM: C[M,Ntot] = A[M,KD] * B[Ntot,KD]^T ----------------
// bf16 hi/lo 3-pass (Ah*Bh + Ah*Bl + Al*Bh) into fp32 accumulators.
// CTA tile 128x128, 8 warps of 32(M)x64(N), BK=32, ldmatrix from stride-40 smem.
#define SSTR 40   // smem row stride in bf16 elems (80B, conflict-free ldmatrix)

template <int KD>
__global__ __launch_bounds__(256)
void k_mma_gemm(const __nv_bfloat16* __restrict__ Ah, const __nv_bfloat16* __restrict__ Al,
                const __nv_bfloat16* __restrict__ Bh, const __nv_bfloat16* __restrict__ Bl,
                float* __restrict__ C, int Mreal, int ldc)
{
    __shared__ __nv_bfloat16 sAh[128 * SSTR];
    __shared__ __nv_bfloat16 sAl[128 * SSTR];
    __shared__ __nv_bfloat16 sBh[128 * SSTR];
    __shared__ __nv_bfloat16 sBl[128 * SSTR];

    const int tid  = threadIdx.x;
    const int wid  = tid >> 5;
    const int lane = tid & 31;
    const int m0 = blockIdx.y * 128;
    const int j0 = blockIdx.x * 128;
    const int warp_m = (wid & 3) * 32;   // 0,32,64,96
    const int warp_n = (wid >> 2) * 64;  // 0,64

    const uint32_t bAh = smem_u32(sAh), bAl = smem_u32(sAl);
    const uint32_t bBh = smem_u32(sBh), bBl = smem_u32(sBl);

    // per-lane ldmatrix row components
    const int ar = lane & 15;            // row within 16
    const int kh = (lane >> 4) << 3;     // k half offset (0 or 8)

    float acc[2][8][4];
    #pragma unroll
    for (int i = 0; i < 2; i++)
        #pragma unroll
        for (int j = 0; j < 8; j++)
            #pragma unroll
            for (int q = 0; q < 4; q++) acc[i][j][q] = 0.0f;

    for (int kt = 0; kt < KD; kt += 32) {
        // cooperative load: each tile 128x32 bf16 = 512 uint4; 2 per thread per tile
        #pragma unroll
        for (int i = 0; i < 2; i++) {
            int v = tid + i * 256;
            int row = v >> 2;
            int c8 = (v & 3) << 3;
            size_t ga = (size_t)(m0 + row) * KD + kt + c8;
            size_t gb = (size_t)(j0 + row) * KD + kt + c8;
            int so = row * SSTR + c8;
            *(uint4*)(sAh + so) = *(const uint4*)(Ah + ga);
            *(uint4*)(sAl + so) = *(const uint4*)(Al + ga);
            *(uint4*)(sBh + so) = *(const uint4*)(Bh + gb);
            *(uint4*)(sBl + so) = *(const uint4*)(Bl + gb);
        }
        __syncthreads();

        #pragma unroll
        for (int pass = 0; pass < 3; pass++) {
            uint32_t aBase = (pass == 2) ? bAl : bAh;
            uint32_t bBase = (pass == 1) ? bBl : bBh;
            #pragma unroll
            for (int k16 = 0; k16 < 2; k16++) {
                uint32_t kb = (uint32_t)((k16 * 16 + kh) * 2);
                // A frags: 2 m16 tiles
                uint32_t a[2][4];
                #pragma unroll
                for (int mi = 0; mi < 2; mi++) {
                    uint32_t ad = aBase + (uint32_t)((warp_m + mi * 16 + ar) * SSTR * 2) + kb;
                    ldsm_x4(a[mi][0], a[mi][1], a[mi][2], a[mi][3], ad);
                }
                // B frags: 4 n16 groups -> 8 n8 frags
                uint32_t b[8][2];
                #pragma unroll
                for (int ng = 0; ng < 4; ng++) {
                    uint32_t r0, r1, r2, r3;
                    uint32_t bd = bBase + (uint32_t)((warp_n + ng * 16 + ar) * SSTR * 2) + kb;
                    ldsm_x4(r0, r1, r2, r3, bd);
                    b[ng * 2][0] = r0;     b[ng * 2][1] = r2;
                    b[ng * 2 + 1][0] = r1; b[ng * 2 + 1][1] = r3;
                }
                #pragma unroll
                for (int mi = 0; mi < 2; mi++)
                    #pragma unroll
                    for (int nj = 0; nj < 8; nj++)
                        mma_bf16(acc[mi][nj], a[mi], b[nj]);
            }
        }
        __syncthreads();
    }

    // epilogue: acc[mi][nj] = m16n8 fragment
    const int rg = lane >> 2;       // row in group
    const int tg = lane & 3;        // col pair
    #pragma unroll
    for (int mi = 0; mi < 2; mi++) {
        int r0 = m0 + warp_m + mi * 16 + rg;
        int r1 = r0 + 8;
        #pragma unroll
        for (int nj = 0; nj < 8; nj++) {
            int col = j0 + warp_n + nj * 8 + tg * 2;
            if (r0 < Mreal) {
                float2 v = {acc[mi][nj][0], acc[mi][nj][1]};
                *(float2*)(C + (size_t)r0 * ldc + col) = v;
            }
            if (r1 < Mreal) {
                float2 v = {acc[mi][nj][2], acc[mi][nj][3]};
                *(float2*)(C + (size_t)r1 * ldc + col) = v;
            }
        }
    }
}

// ---------------- fused node kernel: scores + normalize + weighted V agg ----------------
__global__ __launch_bounds__(256)
void k_node(const int* __restrict__ esrc, const int* __restrict__ erel, int N)
{
    int warp = (blockIdx.x * blockDim.x + threadIdx.x) >> 5;
    int lane = threadIdx.x & 31;
    if (warp >= N) return;

    const int start = g_rowptr[warp];
    const int end   = g_rowptr[warp + 1];

    const float4* qp = (const float4*)(g_qkv + (size_t)warp * NJQKV + lane * 8);
    float4 qa = qp[0], qb = qp[1];

    float den = 0.0f;
    for (int j = start; j < end; j++) {
        int e = g_eid[j];
        int src = esrc[e];
        int rel = erel[e];
        const float4* kp = (const float4*)(g_qkv + (size_t)src * NJQKV + 256 + rel * 256 + lane * 8);
        float4 ka = kp[0], kb = kp[1];
        float p = qa.x * ka.x + qa.y * ka.y + qa.z * ka.z + qa.w * ka.w
                + qb.x * kb.x + qb.y * kb.y + qb.z * kb.z + qb.w * kb.w;
        #pragma unroll
        for (int off = 8; off >= 1; off >>= 1)
            p += __shfl_xor_sync(0xffffffffu, p, off);
        if (lane == 0 || lane == 16) {
            float s = p / SCALE;
            float nu = fmaxf(s, 0.0f);
            nu = nu * nu + 1e-10f;
            g_numer[2 * e + (lane >> 4)] = nu;
            den += nu;
        }
    }
    float dall = __shfl_sync(0xffffffffu, den, (lane >> 4) << 4);
    float inv = (dall > 0.0f) ? 1.0f / dall : 0.0f;

    float4 acc0 = {0, 0, 0, 0}, acc1 = {0, 0, 0, 0};
    for (int j = start; j < end; j++) {
        int e = g_eid[j];
        int src = esrc[e];
        int rel = erel[e];
        float nv = 0.0f;
        if (lane == 0)  nv = g_numer[2 * e];
        if (lane == 16) nv = g_numer[2 * e + 1];
        float w = __shfl_sync(0xffffffffu, nv, (lane >> 4) << 4) * inv;
        const float4* vp = (const float4*)(g_qkv + (size_t)src * NJQKV + 1024 + rel * 256 + lane * 8);
        float4 v0 = vp[0], v1 = vp[1];
        acc0.x += w * v0.x; acc0.y += w * v0.y; acc0.z += w * v0.z; acc0.w += w * v0.w;
        acc1.x += w * v1.x; acc1.y += w * v1.y; acc1.z += w * v1.z; acc1.w += w * v1.w;
    }

    size_t zb = (size_t)warp * HD + lane * 8;
    float a[8] = {acc0.x, acc0.y, acc0.z, acc0.w, acc1.x, acc1.y, acc1.z, acc1.w};
    #pragma unroll
    for (int i = 0; i < 8; i++) {
        __nv_bfloat16 hi = __float2bfloat16(a[i]);
        g_zh[zb + i] = hi;
        g_zl[zb + i] = __float2bfloat16(a[i] - __bfloat162float(hi));
    }
}

// ---------------- launch ----------------
extern "C" void kernel_launch(void* const* d_in, const int* in_sizes, int n_in,
                              void* d_out, int out_size)
{
    const float* X   = (const float*)d_in[0];
    const float* WQ  = (const float*)d_in[1];
    const float* WK  = (const float*)d_in[2];
    const float* WV  = (const float*)d_in[3];
    const float* WO  = (const float*)d_in[4];
    const int*  esrc = (const int*)d_in[5];
    const int*  edst = (const int*)d_in[6];
    const int*  erel = (const int*)d_in[7];
    float* out = (float*)d_out;

    const int N = NN, E = EE;

    float* qkv; cudaGetSymbolAddress((void**)&qkv, g_qkv);
    __nv_bfloat16 *xh, *xl, *wh, *wl, *woh, *wol, *zh, *zl;
    cudaGetSymbolAddress((void**)&xh,  g_xh);
    cudaGetSymbolAddress((void**)&xl,  g_xl);
    cudaGetSymbolAddress((void**)&wh,  g_wh);
    cudaGetSymbolAddress((void**)&wl,  g_wl);
    cudaGetSymbolAddress((void**)&woh, g_woh);
    cudaGetSymbolAddress((void**)&wol, g_wol);
    cudaGetSymbolAddress((void**)&zh,  g_zh);
    cudaGetSymbolAddress((void**)&zl,  g_zl);

    // 1. init + conversions
    k_init<<<((MPAD - NN) * HD + 255) / 256, 256>>>();
    k_split<<<(MPAD * DD + 255) / 256, 256>>>(X, xh, xl, N * DD, MPAD * DD);
    k_split<<<(256 * DD + 255) / 256, 256>>>(WQ, wh, wl, 256 * DD, 256 * DD);
    k_split<<<(768 * DD + 255) / 256, 256>>>(WK, wh + 256 * DD, wl + 256 * DD, 768 * DD, 768 * DD);
    k_split<<<(768 * DD + 255) / 256, 256>>>(WV, wh + 1024 * DD, wl + 1024 * DD, 768 * DD, 768 * DD);
    k_split<<<(DD * HD + 255) / 256, 256>>>(WO, woh, wol, DD * HD, DD * HD);

    // 2. CSR build
    k_deg<<<(E + 255) / 256, 256>>>(edst, E);
    k_scan<<<1, 1024>>>(N);
    k_scatter<<<(E + 255) / 256, 256>>>(edst, E);

    // 3. fused projection GEMM: [MPAD,128] x [1792,128]^T -> g_qkv
    {
        dim3 grid(NJQKV / 128, MPAD / 128);
        k_mma_gemm<DD><<<grid, 256>>>(xh, xl, wh, wl, qkv, N, NJQKV);
    }

    // 4. fused node pass: scores + denom + weighted aggregation -> z hi/lo
    k_node<<<(N + 7) / 8, 256>>>(esrc, erel, N);

    // 5. output GEMM: [MPAD,256] x [128,256]^T -> out
    {
        dim3 grid(1, MPAD / 128);
        k_mma_gemm<HD><<<grid, 256>>>(zh, zl, woh, wol, out, N, DD);
    }
}

// round 5
// speedup vs baseline: 1.5050x; 1.0934x over previous
#include <cuda_runtime.h>
#include <cuda_bf16.h>
#include <cstdint>

// Problem constants (fixed by the dataset)
#define NN    20000
#define MPAD  20096        // 157 * 128
#define EE    320000
#define DD    128
#define HD    256
#define NQK   1024         // Q(256) + K(3*256)
#define YW    768          // 3 rel * 2 head * 128
#define SCALE 16.0f

// ---------------- scratch (device globals; no allocation) ----------------
__device__ float          g_qk[(size_t)NN * NQK];     // fp32 [N,1024]: Q | K(r0..2)
__device__ __nv_bfloat16  g_xh[(size_t)MPAD * DD];
__device__ __nv_bfloat16  g_xl[(size_t)MPAD * DD];
__device__ __nv_bfloat16  g_wh[(size_t)NQK * DD];
__device__ __nv_bfloat16  g_wl[(size_t)NQK * DD];
__device__ float          g_wfin[(size_t)DD * YW];    // fused WO*WV  [128,768]
__device__ __nv_bfloat16  g_wfh[(size_t)DD * YW];
__device__ __nv_bfloat16  g_wfl[(size_t)DD * YW];
__device__ __nv_bfloat16  g_yh[(size_t)MPAD * YW];    // weighted-x aggregate hi/lo
__device__ __nv_bfloat16  g_yl[(size_t)MPAD * YW];
__device__ int   g_deg[NN];
__device__ int   g_rowptr[NN + 1];
__device__ int   g_cursor[NN];
__device__ int   g_eid[EE];

__device__ __forceinline__ uint32_t smem_u32(const void* p) {
    uint32_t a;
    asm("{ .reg .u64 t; cvta.to.shared.u64 t, %1; cvt.u32.u64 %0, t; }" : "=r"(a) : "l"(p));
    return a;
}
__device__ __forceinline__ void ldsm_x4(uint32_t& r0, uint32_t& r1, uint32_t& r2, uint32_t& r3,
                                        uint32_t addr) {
    asm volatile("ldmatrix.sync.aligned.m8n8.x4.shared.b16 {%0,%1,%2,%3}, [%4];"
                 : "=r"(r0), "=r"(r1), "=r"(r2), "=r"(r3) : "r"(addr));
}
__device__ __forceinline__ void mma_bf16(float* d, const uint32_t* a, const uint32_t* b) {
    asm volatile(
        "mma.sync.aligned.m16n8k16.row.col.f32.bf16.bf16.f32 "
        "{%0,%1,%2,%3}, {%4,%5,%6,%7}, {%8,%9}, {%0,%1,%2,%3};"
        : "+f"(d[0]), "+f"(d[1]), "+f"(d[2]), "+f"(d[3])
        : "r"(a[0]), "r"(a[1]), "r"(a[2]), "r"(a[3]), "r"(b[0]), "r"(b[1]));
}
#define CP_ASYNC16(dst, src) \
    asm volatile("cp.async.cg.shared.global [%0], [%1], 16;\n" :: "r"(dst), "l"(src))
#define CP_COMMIT() asm volatile("cp.async.commit_group;\n" ::: "memory")
#define CP_WAIT(n)  asm volatile("cp.async.wait_group %0;\n" :: "n"(n) : "memory")

// ---------------- init ----------------
__global__ void k_init()
{
    int i = blockIdx.x * blockDim.x + threadIdx.x;
    if (i < NN) { g_deg[i] = 0; g_cursor[i] = 0; }
    int padn = (MPAD - NN) * YW;   // 73728
    if (i < padn) {
        g_yh[(size_t)NN * YW + i] = __float2bfloat16(0.0f);
        g_yl[(size_t)NN * YW + i] = __float2bfloat16(0.0f);
    }
}

// ---------------- fp32 -> bf16 hi/lo split ----------------
__global__ void k_split(const float* __restrict__ s, __nv_bfloat16* __restrict__ h,
                        __nv_bfloat16* __restrict__ l, int nreal, int ntot)
{
    int i = blockIdx.x * blockDim.x + threadIdx.x;
    if (i >= ntot) return;
    float x = (i < nreal) ? s[i] : 0.0f;
    __nv_bfloat16 hi = __float2bfloat16(x);
    float lo = x - __bfloat162float(hi);
    h[i] = hi;
    l[i] = __float2bfloat16(lo);
}

// ---------------- Wfin[o, (r*2+h)*128+k] = sum_d WO[o,h*128+d] * WV[r,h*128+d,k] ----------------
__global__ void k_wfin(const float* __restrict__ WO, const float* __restrict__ WV)
{
    int rh = blockIdx.x;          // 0..5
    int o  = blockIdx.y;          // 0..127
    int k  = threadIdx.x;         // 0..127
    int r = rh >> 1, h = rh & 1;
    const float* wo = WO + o * HD + h * 128;
    const float* wv = WV + ((size_t)(r * HD + h * 128)) * DD + k;
    float acc = 0.0f;
    #pragma unroll 8
    for (int d = 0; d < 128; d++)
        acc = fmaf(wo[d], wv[(size_t)d * DD], acc);
    g_wfin[(size_t)o * YW + rh * 128 + k] = acc;
}

// ---------------- degree histogram ----------------
__global__ void k_deg(const int* __restrict__ edst, int E)
{
    int e = blockIdx.x * blockDim.x + threadIdx.x;
    if (e < E) atomicAdd(&g_deg[edst[e]], 1);
}

// ---------------- fast scan ----------------
__global__ __launch_bounds__(1024) void k_scan(int n)
{
    const int P = 20;
    __shared__ int wsum[32];
    int tid = threadIdx.x, lane = tid & 31, wid = tid >> 5;
    int base = tid * P;
    int v[P];
    int s = 0;
    #pragma unroll
    for (int i = 0; i < P; i++) {
        int idx = base + i;
        int d = (idx < n) ? g_deg[idx] : 0;
        s += d;
        v[i] = s;
    }
    int x = s;
    #pragma unroll
    for (int off = 1; off < 32; off <<= 1) {
        int t = __shfl_up_sync(0xffffffffu, x, off);
        if (lane >= off) x += t;
    }
    if (lane == 31) wsum[wid] = x;
    __syncthreads();
    if (wid == 0) {
        int y = wsum[lane];
        #pragma unroll
        for (int off = 1; off < 32; off <<= 1) {
            int t = __shfl_up_sync(0xffffffffu, y, off);
            if (lane >= off) y += t;
        }
        wsum[lane] = y;
    }
    __syncthreads();
    int offset = (wid ? wsum[wid - 1] : 0) + x - s;
    if (tid == 0) g_rowptr[0] = 0;
    #pragma unroll
    for (int i = 0; i < P; i++) {
        int idx = base + i;
        if (idx < n) g_rowptr[idx + 1] = offset + v[i];
    }
}

// ---------------- scatter edges into CSR ----------------
__global__ void k_scatter(const int* __restrict__ edst, int E)
{
    int e = blockIdx.x * blockDim.x + threadIdx.x;
    if (e >= E) return;
    int dst = edst[e];
    int pos = atomicAdd(&g_cursor[dst], 1);
    g_eid[g_rowptr[dst] + pos] = e;
}

// ---------------- mma.sync GEMM, cp.async double-buffered ----------------
// C[M,Ntot] = A[M,KD]*B[Ntot,KD]^T, bf16 hi/lo 3-pass into fp32.
// CTA 128x128, 8 warps 32x64, BK=32, smem stride 40 elems (conflict-free ldmatrix).
#define SSTR   40
#define TILEB  10240                 // 128*40*2 bytes per tile
#define STAGEB (4 * TILEB)           // Ah,Al,Bh,Bl
#define GSMEM  (2 * STAGEB)          // 81920 B

template <int KD>
__global__ __launch_bounds__(256)
void k_mma_gemm(const __nv_bfloat16* __restrict__ Ah, const __nv_bfloat16* __restrict__ Al,
                const __nv_bfloat16* __restrict__ Bh, const __nv_bfloat16* __restrict__ Bl,
                float* __restrict__ C, int Mreal, int ldc)
{
    extern __shared__ uint8_t dsm[];
    const uint32_t sb = smem_u32(dsm);
    const int tid  = threadIdx.x;
    const int wid  = tid >> 5;
    const int lane = tid & 31;
    const int m0 = blockIdx.y * 128;
    const int j0 = blockIdx.x * 128;
    const int warp_m = (wid & 3) * 32;
    const int warp_n = (wid >> 2) * 64;

    const int ar = lane & 15;
    const int kh = (lane >> 4) << 3;

    float acc[2][8][4];
    #pragma unroll
    for (int i = 0; i < 2; i++)
        #pragma unroll
        for (int j = 0; j < 8; j++)
            #pragma unroll
            for (int q = 0; q < 4; q++) acc[i][j][q] = 0.0f;

    // per-thread load coordinates (2 uint4 per tile array)
    int rowA[2], c8A[2];
    #pragma unroll
    for (int i = 0; i < 2; i++) {
        int v = tid + i * 256;
        rowA[i] = v >> 2;
        c8A[i] = (v & 3) << 3;
    }

    auto prefetch = [&](int kt, int stage) {
        uint32_t base = sb + (uint32_t)stage * STAGEB;
        #pragma unroll
        for (int i = 0; i < 2; i++) {
            int row = rowA[i], c8 = c8A[i];
            uint32_t so = base + (uint32_t)(row * SSTR + c8) * 2;
            size_t ga = (size_t)(m0 + row) * KD + kt + c8;
            size_t gb = (size_t)(j0 + row) * KD + kt + c8;
            CP_ASYNC16(so,             Ah + ga);
            CP_ASYNC16(so + TILEB,     Al + ga);
            CP_ASYNC16(so + 2 * TILEB, Bh + gb);
            CP_ASYNC16(so + 3 * TILEB, Bl + gb);
        }
        CP_COMMIT();
    };

    constexpr int NCH = KD / 32;
    prefetch(0, 0);

    for (int ch = 0; ch < NCH; ch++) {
        if (ch + 1 < NCH) {
            prefetch((ch + 1) * 32, (ch + 1) & 1);
            CP_WAIT(1);
        } else {
            CP_WAIT(0);
        }
        __syncthreads();

        uint32_t base = sb + (uint32_t)(ch & 1) * STAGEB;
        #pragma unroll
        for (int pass = 0; pass < 3; pass++) {
            uint32_t aBase = base + (pass == 2 ? TILEB : 0u);
            uint32_t bBase = base + 2 * TILEB + (pass == 1 ? TILEB : 0u);
            #pragma unroll
            for (int k16 = 0; k16 < 2; k16++) {
                uint32_t kb = (uint32_t)((k16 * 16 + kh) * 2);
                uint32_t a[2][4];
                #pragma unroll
                for (int mi = 0; mi < 2; mi++) {
                    uint32_t ad = aBase + (uint32_t)((warp_m + mi * 16 + ar) * SSTR * 2) + kb;
                    ldsm_x4(a[mi][0], a[mi][1], a[mi][2], a[mi][3], ad);
                }
                uint32_t b[8][2];
                #pragma unroll
                for (int ng = 0; ng < 4; ng++) {
                    uint32_t r0, r1, r2, r3;
                    uint32_t bd = bBase + (uint32_t)((warp_n + ng * 16 + ar) * SSTR * 2) + kb;
                    ldsm_x4(r0, r1, r2, r3, bd);
                    b[ng * 2][0] = r0;     b[ng * 2][1] = r2;
                    b[ng * 2 + 1][0] = r1; b[ng * 2 + 1][1] = r3;
                }
                #pragma unroll
                for (int mi = 0; mi < 2; mi++)
                    #pragma unroll
                    for (int nj = 0; nj < 8; nj++)
                        mma_bf16(acc[mi][nj], a[mi], b[nj]);
            }
        }
        __syncthreads();
    }

    const int rg = lane >> 2;
    const int tg = lane & 3;
    #pragma unroll
    for (int mi = 0; mi < 2; mi++) {
        int r0 = m0 + warp_m + mi * 16 + rg;
        int r1 = r0 + 8;
        #pragma unroll
        for (int nj = 0; nj < 8; nj++) {
            int col = j0 + warp_n + nj * 8 + tg * 2;
            if (r0 < Mreal) {
                float2 v = {acc[mi][nj][0], acc[mi][nj][1]};
                *(float2*)(C + (size_t)r0 * ldc + col) = v;
            }
            if (r1 < Mreal) {
                float2 v = {acc[mi][nj][2], acc[mi][nj][3]};
                *(float2*)(C + (size_t)r1 * ldc + col) = v;
            }
        }
    }
}

// ---------------- fused node kernel (single pass) ----------------
// scores + denom + unnormalized weighted-x aggregation, scale at end.
// one warp per dst node; lanes 0-15 head0, 16-31 head1 for scoring;
// all 32 lanes cover 128 x-dims (4 each) for Y accumulation.
__global__ __launch_bounds__(256)
void k_node(const float* __restrict__ X, const int* __restrict__ esrc,
            const int* __restrict__ erel, int N)
{
    int warp = (blockIdx.x * blockDim.x + threadIdx.x) >> 5;
    int lane = threadIdx.x & 31;
    if (warp >= N) return;

    const int start = g_rowptr[warp];
    const int end   = g_rowptr[warp + 1];

    const float4* qp = (const float4*)(g_qk + (size_t)warp * NQK + lane * 8);
    float4 qa = qp[0], qb = qp[1];

    float y[3][2][4];
    #pragma unroll
    for (int r = 0; r < 3; r++)
        #pragma unroll
        for (int h = 0; h < 2; h++)
            #pragma unroll
            for (int i = 0; i < 4; i++) y[r][h][i] = 0.0f;

    float den0 = 0.0f, den1 = 0.0f;

    for (int j = start; j < end; j++) {
        int e   = g_eid[j];
        int src = esrc[e];
        int rel = erel[e];

        const float4* kp = (const float4*)(g_qk + (size_t)src * NQK + 256 + rel * 256 + lane * 8);
        float4 ka = kp[0], kb = kp[1];
        float p = qa.x * ka.x + qa.y * ka.y + qa.z * ka.z + qa.w * ka.w
                + qb.x * kb.x + qb.y * kb.y + qb.z * kb.z + qb.w * kb.w;
        #pragma unroll
        for (int off = 8; off >= 1; off >>= 1)
            p += __shfl_xor_sync(0xffffffffu, p, off);
        float s = p / SCALE;
        float nu = fmaxf(s, 0.0f);
        nu = nu * nu + 1e-10f;
        float nu0 = __shfl_sync(0xffffffffu, nu, 0);
        float nu1 = __shfl_sync(0xffffffffu, nu, 16);
        den0 += nu0;
        den1 += nu1;

        float4 xv = *(const float4*)(X + (size_t)src * DD + lane * 4);
        float xa[4] = {xv.x, xv.y, xv.z, xv.w};
        if (rel == 0) {
            #pragma unroll
            for (int i = 0; i < 4; i++) { y[0][0][i] += nu0 * xa[i]; y[0][1][i] += nu1 * xa[i]; }
        } else if (rel == 1) {
            #pragma unroll
            for (int i = 0; i < 4; i++) { y[1][0][i] += nu0 * xa[i]; y[1][1][i] += nu1 * xa[i]; }
        } else {
            #pragma unroll
            for (int i = 0; i < 4; i++) { y[2][0][i] += nu0 * xa[i]; y[2][1][i] += nu1 * xa[i]; }
        }
    }

    float inv0 = (den0 > 0.0f) ? 1.0f / den0 : 0.0f;
    float inv1 = (den1 > 0.0f) ? 1.0f / den1 : 0.0f;

    #pragma unroll
    for (int r = 0; r < 3; r++)
        #pragma unroll
        for (int h = 0; h < 2; h++) {
            float sc = h ? inv1 : inv0;
            size_t off = (size_t)warp * YW + (r * 2 + h) * 128 + lane * 4;
            #pragma unroll
            for (int i = 0; i < 4; i++) {
                float val = y[r][h][i] * sc;
                __nv_bfloat16 hi = __float2bfloat16(val);
                g_yh[off + i] = hi;
                g_yl[off + i] = __float2bfloat16(val - __bfloat162float(hi));
            }
        }
}

// ---------------- launch ----------------
extern "C" void kernel_launch(void* const* d_in, const int* in_sizes, int n_in,
                              void* d_out, int out_size)
{
    const float* X   = (const float*)d_in[0];
    const float* WQ  = (const float*)d_in[1];
    const float* WK  = (const float*)d_in[2];
    const float* WV  = (const float*)d_in[3];
    const float* WO  = (const float*)d_in[4];
    const int*  esrc = (const int*)d_in[5];
    const int*  edst = (const int*)d_in[6];
    const int*  erel = (const int*)d_in[7];
    float* out = (float*)d_out;

    const int N = NN, E = EE;

    float *qk, *wfin;
    cudaGetSymbolAddress((void**)&qk,   g_qk);
    cudaGetSymbolAddress((void**)&wfin, g_wfin);
    __nv_bfloat16 *xh, *xl, *wh, *wl, *wfh, *wfl, *yh, *yl;
    cudaGetSymbolAddress((void**)&xh,  g_xh);
    cudaGetSymbolAddress((void**)&xl,  g_xl);
    cudaGetSymbolAddress((void**)&wh,  g_wh);
    cudaGetSymbolAddress((void**)&wl,  g_wl);
    cudaGetSymbolAddress((void**)&wfh, g_wfh);
    cudaGetSymbolAddress((void**)&wfl, g_wfl);
    cudaGetSymbolAddress((void**)&yh,  g_yh);
    cudaGetSymbolAddress((void**)&yl,  g_yl);

    cudaFuncSetAttribute(k_mma_gemm<DD>, cudaFuncAttributeMaxDynamicSharedMemorySize, GSMEM);
    cudaFuncSetAttribute(k_mma_gemm<YW>, cudaFuncAttributeMaxDynamicSharedMemorySize, GSMEM);

    // 1. init + conversions
    k_init<<<((MPAD - NN) * YW + 255) / 256, 256>>>();
    k_split<<<(MPAD * DD + 255) / 256, 256>>>(X, xh, xl, N * DD, MPAD * DD);
    k_split<<<(256 * DD + 255) / 256, 256>>>(WQ, wh, wl, 256 * DD, 256 * DD);
    k_split<<<(768 * DD + 255) / 256, 256>>>(WK, wh + 256 * DD, wl + 256 * DD, 768 * DD, 768 * DD);

    // 2. fused output weights: Wfin = WO x WV  (then split)
    {
        dim3 grid(6, 128);
        k_wfin<<<grid, 128>>>(WO, WV);
    }
    k_split<<<(DD * YW + 255) / 256, 256>>>(wfin, wfh, wfl, DD * YW, DD * YW);

    // 3. CSR build
    k_deg<<<(E + 255) / 256, 256>>>(edst, E);
    k_scan<<<1, 1024>>>(N);
    k_scatter<<<(E + 255) / 256, 256>>>(edst, E);

    // 4. projection GEMM: [MPAD,128] x [1024,128]^T -> g_qk
    {
        dim3 grid(NQK / 128, MPAD / 128);
        k_mma_gemm<DD><<<grid, 256, GSMEM>>>(xh, xl, wh, wl, qk, N, NQK);
    }

    // 5. fused node pass: scores + denom + weighted-x aggregation -> Y hi/lo
    k_node<<<(N + 7) / 8, 256>>>(X, esrc, erel, N);

    // 6. final GEMM: [MPAD,768] x [128,768]^T -> out
    {
        dim3 grid(1, MPAD / 128);
        k_mma_gemm<YW><<<grid, 256, GSMEM>>>(yh, yl, wfh, wfl, out, N, DD);
    }
}

// round 6
// speedup vs baseline: 1.7282x; 1.1483x over previous
#include <cuda_runtime.h>
#include <cuda_bf16.h>
#include <cstdint>

// Problem constants (fixed by the dataset)
#define NN    20000
#define MPAD  20096        // 157 * 128
#define EE    320000
#define DD    128
#define HD    256
#define NQK   1024         // Q(256) + K(3*256)
#define YW    768          // 3 rel * 2 head * 128
#define SCALE 16.0f

// ---------------- scratch (device globals; no allocation) ----------------
__device__ float          g_qk[(size_t)NN * NQK];     // fp32 [N,1024]: Q | K(r0..2)
__device__ __nv_bfloat16  g_xh[(size_t)MPAD * DD];
__device__ __nv_bfloat16  g_xl[(size_t)MPAD * DD];
__device__ __nv_bfloat16  g_wh[(size_t)NQK * DD];
__device__ __nv_bfloat16  g_wl[(size_t)NQK * DD];
__device__ __nv_bfloat16  g_wfh[(size_t)DD * YW];
__device__ __nv_bfloat16  g_wfl[(size_t)DD * YW];
__device__ __nv_bfloat16  g_yh[(size_t)MPAD * YW];    // weighted-x aggregate hi/lo
__device__ __nv_bfloat16  g_yl[(size_t)MPAD * YW];
__device__ int   g_deg[NN];
__device__ int   g_rowptr[NN + 1];
__device__ int   g_cursor[NN];
__device__ int   g_pack[EE];                          // CSR-ordered src | (rel<<15)

__device__ __forceinline__ uint32_t smem_u32(const void* p) {
    uint32_t a;
    asm("{ .reg .u64 t; cvta.to.shared.u64 t, %1; cvt.u32.u64 %0, t; }" : "=r"(a) : "l"(p));
    return a;
}
__device__ __forceinline__ void ldsm_x4(uint32_t& r0, uint32_t& r1, uint32_t& r2, uint32_t& r3,
                                        uint32_t addr) {
    asm volatile("ldmatrix.sync.aligned.m8n8.x4.shared.b16 {%0,%1,%2,%3}, [%4];"
                 : "=r"(r0), "=r"(r1), "=r"(r2), "=r"(r3) : "r"(addr));
}
__device__ __forceinline__ void mma_bf16(float* d, const uint32_t* a, const uint32_t* b) {
    asm volatile(
        "mma.sync.aligned.m16n8k16.row.col.f32.bf16.bf16.f32 "
        "{%0,%1,%2,%3}, {%4,%5,%6,%7}, {%8,%9}, {%0,%1,%2,%3};"
        : "+f"(d[0]), "+f"(d[1]), "+f"(d[2]), "+f"(d[3])
        : "r"(a[0]), "r"(a[1]), "r"(a[2]), "r"(a[3]), "r"(b[0]), "r"(b[1]));
}
#define CP_ASYNC16(dst, src) \
    asm volatile("cp.async.cg.shared.global [%0], [%1], 16;\n" :: "r"(dst), "l"(src))
#define CP_COMMIT() asm volatile("cp.async.commit_group;\n" ::: "memory")
#define CP_WAIT(n)  asm volatile("cp.async.wait_group %0;\n" :: "n"(n) : "memory")

// ---------------- init ----------------
__global__ void k_init()
{
    int i = blockIdx.x * blockDim.x + threadIdx.x;
    if (i < NN) { g_deg[i] = 0; g_cursor[i] = 0; }
    int padn = (MPAD - NN) * YW;   // 73728
    if (i < padn) {
        g_yh[(size_t)NN * YW + i] = __float2bfloat16(0.0f);
        g_yl[(size_t)NN * YW + i] = __float2bfloat16(0.0f);
    }
}

// ---------------- fp32 -> bf16 hi/lo split ----------------
__global__ void k_split(const float* __restrict__ s, __nv_bfloat16* __restrict__ h,
                        __nv_bfloat16* __restrict__ l, int nreal, int ntot)
{
    int i = blockIdx.x * blockDim.x + threadIdx.x;
    if (i >= ntot) return;
    float x = (i < nreal) ? s[i] : 0.0f;
    __nv_bfloat16 hi = __float2bfloat16(x);
    float lo = x - __bfloat162float(hi);
    h[i] = hi;
    l[i] = __float2bfloat16(lo);
}

// ---------------- Wfin[o,(r*2+h)*128+k] = sum_d WO[o,h*128+d]*WV[r,h*128+d,k]; hi/lo out ----------------
__global__ void k_wfin(const float* __restrict__ WO, const float* __restrict__ WV)
{
    int rh = blockIdx.x;          // 0..5
    int o  = blockIdx.y;          // 0..127
    int k  = threadIdx.x;         // 0..127
    int r = rh >> 1, h = rh & 1;
    const float* wo = WO + o * HD + h * 128;
    const float* wv = WV + ((size_t)(r * HD + h * 128)) * DD + k;
    float acc = 0.0f;
    #pragma unroll 8
    for (int d = 0; d < 128; d++)
        acc = fmaf(wo[d], wv[(size_t)d * DD], acc);
    size_t idx = (size_t)o * YW + rh * 128 + k;
    __nv_bfloat16 hi = __float2bfloat16(acc);
    g_wfh[idx] = hi;
    g_wfl[idx] = __float2bfloat16(acc - __bfloat162float(hi));
}

// ---------------- degree histogram ----------------
__global__ void k_deg(const int* __restrict__ edst, int E)
{
    int e = blockIdx.x * blockDim.x + threadIdx.x;
    if (e < E) atomicAdd(&g_deg[edst[e]], 1);
}

// ---------------- fast scan ----------------
__global__ __launch_bounds__(1024) void k_scan(int n)
{
    const int P = 20;
    __shared__ int wsum[32];
    int tid = threadIdx.x, lane = tid & 31, wid = tid >> 5;
    int base = tid * P;
    int v[P];
    int s = 0;
    #pragma unroll
    for (int i = 0; i < P; i++) {
        int idx = base + i;
        int d = (idx < n) ? g_deg[idx] : 0;
        s += d;
        v[i] = s;
    }
    int x = s;
    #pragma unroll
    for (int off = 1; off < 32; off <<= 1) {
        int t = __shfl_up_sync(0xffffffffu, x, off);
        if (lane >= off) x += t;
    }
    if (lane == 31) wsum[wid] = x;
    __syncthreads();
    if (wid == 0) {
        int y = wsum[lane];
        #pragma unroll
        for (int off = 1; off < 32; off <<= 1) {
            int t = __shfl_up_sync(0xffffffffu, y, off);
            if (lane >= off) y += t;
        }
        wsum[lane] = y;
    }
    __syncthreads();
    int offset = (wid ? wsum[wid - 1] : 0) + x - s;
    if (tid == 0) g_rowptr[0] = 0;
    #pragma unroll
    for (int i = 0; i < P; i++) {
        int idx = base + i;
        if (idx < n) g_rowptr[idx + 1] = offset + v[i];
    }
}

// ---------------- scatter packed src|rel into CSR ----------------
__global__ void k_scatter(const int* __restrict__ esrc, const int* __restrict__ edst,
                          const int* __restrict__ erel, int E)
{
    int e = blockIdx.x * blockDim.x + threadIdx.x;
    if (e >= E) return;
    int dst = edst[e];
    int pos = atomicAdd(&g_cursor[dst], 1);
    g_pack[g_rowptr[dst] + pos] = esrc[e] | (erel[e] << 15);
}

// ---------------- mma.sync GEMM, cp.async double-buffered ----------------
#define SSTR   40
#define TILEB  10240
#define STAGEB (4 * TILEB)
#define GSMEM  (2 * STAGEB)

template <int KD>
__global__ __launch_bounds__(256)
void k_mma_gemm(const __nv_bfloat16* __restrict__ Ah, const __nv_bfloat16* __restrict__ Al,
                const __nv_bfloat16* __restrict__ Bh, const __nv_bfloat16* __restrict__ Bl,
                float* __restrict__ C, int Mreal, int ldc)
{
    extern __shared__ uint8_t dsm[];
    const uint32_t sb = smem_u32(dsm);
    const int tid  = threadIdx.x;
    const int wid  = tid >> 5;
    const int lane = tid & 31;
    const int m0 = blockIdx.y * 128;
    const int j0 = blockIdx.x * 128;
    const int warp_m = (wid & 3) * 32;
    const int warp_n = (wid >> 2) * 64;

    const int ar = lane & 15;
    const int kh = (lane >> 4) << 3;

    float acc[2][8][4];
    #pragma unroll
    for (int i = 0; i < 2; i++)
        #pragma unroll
        for (int j = 0; j < 8; j++)
            #pragma unroll
            for (int q = 0; q < 4; q++) acc[i][j][q] = 0.0f;

    int rowA[2], c8A[2];
    #pragma unroll
    for (int i = 0; i < 2; i++) {
        int v = tid + i * 256;
        rowA[i] = v >> 2;
        c8A[i] = (v & 3) << 3;
    }

    auto prefetch = [&](int kt, int stage) {
        uint32_t base = sb + (uint32_t)stage * STAGEB;
        #pragma unroll
        for (int i = 0; i < 2; i++) {
            int row = rowA[i], c8 = c8A[i];
            uint32_t so = base + (uint32_t)(row * SSTR + c8) * 2;
            size_t ga = (size_t)(m0 + row) * KD + kt + c8;
            size_t gb = (size_t)(j0 + row) * KD + kt + c8;
            CP_ASYNC16(so,             Ah + ga);
            CP_ASYNC16(so + TILEB,     Al + ga);
            CP_ASYNC16(so + 2 * TILEB, Bh + gb);
            CP_ASYNC16(so + 3 * TILEB, Bl + gb);
        }
        CP_COMMIT();
    };

    constexpr int NCH = KD / 32;
    prefetch(0, 0);

    for (int ch = 0; ch < NCH; ch++) {
        if (ch + 1 < NCH) {
            prefetch((ch + 1) * 32, (ch + 1) & 1);
            CP_WAIT(1);
        } else {
            CP_WAIT(0);
        }
        __syncthreads();

        uint32_t base = sb + (uint32_t)(ch & 1) * STAGEB;
        #pragma unroll
        for (int pass = 0; pass < 3; pass++) {
            uint32_t aBase = base + (pass == 2 ? TILEB : 0u);
            uint32_t bBase = base + 2 * TILEB + (pass == 1 ? TILEB : 0u);
            #pragma unroll
            for (int k16 = 0; k16 < 2; k16++) {
                uint32_t kb = (uint32_t)((k16 * 16 + kh) * 2);
                uint32_t a[2][4];
                #pragma unroll
                for (int mi = 0; mi < 2; mi++) {
                    uint32_t ad = aBase + (uint32_t)((warp_m + mi * 16 + ar) * SSTR * 2) + kb;
                    ldsm_x4(a[mi][0], a[mi][1], a[mi][2], a[mi][3], ad);
                }
                uint32_t b[8][2];
                #pragma unroll
                for (int ng = 0; ng < 4; ng++) {
                    uint32_t r0, r1, r2, r3;
                    uint32_t bd = bBase + (uint32_t)((warp_n + ng * 16 + ar) * SSTR * 2) + kb;
                    ldsm_x4(r0, r1, r2, r3, bd);
                    b[ng * 2][0] = r0;     b[ng * 2][1] = r2;
                    b[ng * 2 + 1][0] = r1; b[ng * 2 + 1][1] = r3;
                }
                #pragma unroll
                for (int mi = 0; mi < 2; mi++)
                    #pragma unroll
                    for (int nj = 0; nj < 8; nj++)
                        mma_bf16(acc[mi][nj], a[mi], b[nj]);
            }
        }
        __syncthreads();
    }

    const int rg = lane >> 2;
    const int tg = lane & 3;
    #pragma unroll
    for (int mi = 0; mi < 2; mi++) {
        int r0 = m0 + warp_m + mi * 16 + rg;
        int r1 = r0 + 8;
        #pragma unroll
        for (int nj = 0; nj < 8; nj++) {
            int col = j0 + warp_n + nj * 8 + tg * 2;
            if (r0 < Mreal) {
                float2 v = {acc[mi][nj][0], acc[mi][nj][1]};
                *(float2*)(C + (size_t)r0 * ldc + col) = v;
            }
            if (r1 < Mreal) {
                float2 v = {acc[mi][nj][2], acc[mi][nj][3]};
                *(float2*)(C + (size_t)r1 * ldc + col) = v;
            }
        }
    }
}

// ---------------- fused node kernel: single pass, pipelined, 2-edge unroll ----------------
// one warp per dst node; lanes 0-15 head0, 16-31 head1 for scoring;
// all 32 lanes cover 128 x-dims (4 each) for Y accumulation.
__global__ __launch_bounds__(256)
void k_node(const float* __restrict__ X, int N)
{
    int warp = (blockIdx.x * blockDim.x + threadIdx.x) >> 5;
    int lane = threadIdx.x & 31;
    if (warp >= N) return;

    const int start = g_rowptr[warp];
    const int end   = g_rowptr[warp + 1];

    const float4* qp = (const float4*)(g_qk + (size_t)warp * NQK + lane * 8);
    float4 qa = qp[0], qb = qp[1];

    float y[3][2][4];
    #pragma unroll
    for (int r = 0; r < 3; r++)
        #pragma unroll
        for (int h = 0; h < 2; h++)
            #pragma unroll
            for (int i = 0; i < 4; i++) y[r][h][i] = 0.0f;

    float den0 = 0.0f, den1 = 0.0f;

    int j = start;
    int pk0 = (j < end)     ? g_pack[j]     : 0;
    int pk1 = (j + 1 < end) ? g_pack[j + 1] : 0;

    while (j + 1 < end) {
        int s0 = pk0 & 0x7FFF, r0 = pk0 >> 15;
        int s1 = pk1 & 0x7FFF, r1 = pk1 >> 15;
        int nj = j + 2;
        int npk0 = (nj < end)     ? g_pack[nj]     : 0;
        int npk1 = (nj + 1 < end) ? g_pack[nj + 1] : 0;

        // issue all gathers up front (4 independent streams)
        const float4* kp0 = (const float4*)(g_qk + (size_t)s0 * NQK + 256 + r0 * 256 + lane * 8);
        const float4* kp1 = (const float4*)(g_qk + (size_t)s1 * NQK + 256 + r1 * 256 + lane * 8);
        float4 ka0 = kp0[0], kb0 = kp0[1];
        float4 ka1 = kp1[0], kb1 = kp1[1];
        float4 xv0 = *(const float4*)(X + (size_t)s0 * DD + lane * 4);
        float4 xv1 = *(const float4*)(X + (size_t)s1 * DD + lane * 4);

        float p0 = qa.x * ka0.x + qa.y * ka0.y + qa.z * ka0.z + qa.w * ka0.w
                 + qb.x * kb0.x + qb.y * kb0.y + qb.z * kb0.z + qb.w * kb0.w;
        float p1 = qa.x * ka1.x + qa.y * ka1.y + qa.z * ka1.z + qa.w * ka1.w
                 + qb.x * kb1.x + qb.y * kb1.y + qb.z * kb1.z + qb.w * kb1.w;
        #pragma unroll
        for (int off = 8; off >= 1; off >>= 1) {
            p0 += __shfl_xor_sync(0xffffffffu, p0, off);
            p1 += __shfl_xor_sync(0xffffffffu, p1, off);
        }
        float s0f = p0 / SCALE, s1f = p1 / SCALE;
        float nuA = fmaxf(s0f, 0.0f); nuA = nuA * nuA + 1e-10f;
        float nuB = fmaxf(s1f, 0.0f); nuB = nuB * nuB + 1e-10f;
        float nuA0 = __shfl_sync(0xffffffffu, nuA, 0);
        float nuA1 = __shfl_sync(0xffffffffu, nuA, 16);
        float nuB0 = __shfl_sync(0xffffffffu, nuB, 0);
        float nuB1 = __shfl_sync(0xffffffffu, nuB, 16);
        den0 += nuA0 + nuB0;
        den1 += nuA1 + nuB1;

        float xa0[4] = {xv0.x, xv0.y, xv0.z, xv0.w};
        float xa1[4] = {xv1.x, xv1.y, xv1.z, xv1.w};
        if (r0 == 0) { 
            #pragma unroll
            for (int i = 0; i < 4; i++) { y[0][0][i] += nuA0 * xa0[i]; y[0][1][i] += nuA1 * xa0[i]; }
        } else if (r0 == 1) {
            #pragma unroll
            for (int i = 0; i < 4; i++) { y[1][0][i] += nuA0 * xa0[i]; y[1][1][i] += nuA1 * xa0[i]; }
        } else {
            #pragma unroll
            for (int i = 0; i < 4; i++) { y[2][0][i] += nuA0 * xa0[i]; y[2][1][i] += nuA1 * xa0[i]; }
        }
        if (r1 == 0) {
            #pragma unroll
            for (int i = 0; i < 4; i++) { y[0][0][i] += nuB0 * xa1[i]; y[0][1][i] += nuB1 * xa1[i]; }
        } else if (r1 == 1) {
            #pragma unroll
            for (int i = 0; i < 4; i++) { y[1][0][i] += nuB0 * xa1[i]; y[1][1][i] += nuB1 * xa1[i]; }
        } else {
            #pragma unroll
            for (int i = 0; i < 4; i++) { y[2][0][i] += nuB0 * xa1[i]; y[2][1][i] += nuB1 * xa1[i]; }
        }

        j = nj; pk0 = npk0; pk1 = npk1;
    }

    if (j < end) {
        int s0 = pk0 & 0x7FFF, r0 = pk0 >> 15;
        const float4* kp = (const float4*)(g_qk + (size_t)s0 * NQK + 256 + r0 * 256 + lane * 8);
        float4 ka = kp[0], kb = kp[1];
        float4 xv = *(const float4*)(X + (size_t)s0 * DD + lane * 4);
        float p = qa.x * ka.x + qa.y * ka.y + qa.z * ka.z + qa.w * ka.w
                + qb.x * kb.x + qb.y * kb.y + qb.z * kb.z + qb.w * kb.w;
        #pragma unroll
        for (int off = 8; off >= 1; off >>= 1)
            p += __shfl_xor_sync(0xffffffffu, p, off);
        float s = p / SCALE;
        float nu = fmaxf(s, 0.0f); nu = nu * nu + 1e-10f;
        float nu0 = __shfl_sync(0xffffffffu, nu, 0);
        float nu1 = __shfl_sync(0xffffffffu, nu, 16);
        den0 += nu0;
        den1 += nu1;
        float xa[4] = {xv.x, xv.y, xv.z, xv.w};
        if (r0 == 0) {
            #pragma unroll
            for (int i = 0; i < 4; i++) { y[0][0][i] += nu0 * xa[i]; y[0][1][i] += nu1 * xa[i]; }
        } else if (r0 == 1) {
            #pragma unroll
            for (int i = 0; i < 4; i++) { y[1][0][i] += nu0 * xa[i]; y[1][1][i] += nu1 * xa[i]; }
        } else {
            #pragma unroll
            for (int i = 0; i < 4; i++) { y[2][0][i] += nu0 * xa[i]; y[2][1][i] += nu1 * xa[i]; }
        }
    }

    float inv0 = (den0 > 0.0f) ? 1.0f / den0 : 0.0f;
    float inv1 = (den1 > 0.0f) ? 1.0f / den1 : 0.0f;

    #pragma unroll
    for (int r = 0; r < 3; r++)
        #pragma unroll
        for (int h = 0; h < 2; h++) {
            float sc = h ? inv1 : inv0;
            size_t off = (size_t)warp * YW + (r * 2 + h) * 128 + lane * 4;
            #pragma unroll
            for (int i = 0; i < 4; i++) {
                float val = y[r][h][i] * sc;
                __nv_bfloat16 hi = __float2bfloat16(val);
                g_yh[off + i] = hi;
                g_yl[off + i] = __float2bfloat16(val - __bfloat162float(hi));
            }
        }
}

// ---------------- launch ----------------
extern "C" void kernel_launch(void* const* d_in, const int* in_sizes, int n_in,
                              void* d_out, int out_size)
{
    const float* X   = (const float*)d_in[0];
    const float* WQ  = (const float*)d_in[1];
    const float* WK  = (const float*)d_in[2];
    const float* WV  = (const float*)d_in[3];
    const float* WO  = (const float*)d_in[4];
    const int*  esrc = (const int*)d_in[5];
    const int*  edst = (const int*)d_in[6];
    const int*  erel = (const int*)d_in[7];
    float* out = (float*)d_out;

    const int N = NN, E = EE;

    float* qk;
    cudaGetSymbolAddress((void**)&qk, g_qk);
    __nv_bfloat16 *xh, *xl, *wh, *wl, *wfh, *wfl, *yh, *yl;
    cudaGetSymbolAddress((void**)&xh,  g_xh);
    cudaGetSymbolAddress((void**)&xl,  g_xl);
    cudaGetSymbolAddress((void**)&wh,  g_wh);
    cudaGetSymbolAddress((void**)&wl,  g_wl);
    cudaGetSymbolAddress((void**)&wfh, g_wfh);
    cudaGetSymbolAddress((void**)&wfl, g_wfl);
    cudaGetSymbolAddress((void**)&yh,  g_yh);
    cudaGetSymbolAddress((void**)&yl,  g_yl);

    cudaFuncSetAttribute(k_mma_gemm<DD>, cudaFuncAttributeMaxDynamicSharedMemorySize, GSMEM);
    cudaFuncSetAttribute(k_mma_gemm<YW>, cudaFuncAttributeMaxDynamicSharedMemorySize, GSMEM);

    // 1. init + conversions
    k_init<<<((MPAD - NN) * YW + 255) / 256, 256>>>();
    k_split<<<(MPAD * DD + 255) / 256, 256>>>(X, xh, xl, N * DD, MPAD * DD);
    k_split<<<(256 * DD + 255) / 256, 256>>>(WQ, wh, wl, 256 * DD, 256 * DD);
    k_split<<<(768 * DD + 255) / 256, 256>>>(WK, wh + 256 * DD, wl + 256 * DD, 768 * DD, 768 * DD);

    // 2. fused output weights: Wfin = WO x WV (hi/lo written directly)
    {
        dim3 grid(6, 128);
        k_wfin<<<grid, 128>>>(WO, WV);
    }

    // 3. CSR build
    k_deg<<<(E + 255) / 256, 256>>>(edst, E);
    k_scan<<<1, 1024>>>(N);
    k_scatter<<<(E + 255) / 256, 256>>>(esrc, edst, erel, E);

    // 4. projection GEMM: [MPAD,128] x [1024,128]^T -> g_qk
    {
        dim3 grid(NQK / 128, MPAD / 128);
        k_mma_gemm<DD><<<grid, 256, GSMEM>>>(xh, xl, wh, wl, qk, N, NQK);
    }

    // 5. fused node pass: scores + denom + weighted-x aggregation -> Y hi/lo
    k_node<<<(N + 7) / 8, 256>>>(X, N);

    // 6. final GEMM: [MPAD,768] x [128,768]^T -> out
    {
        dim3 grid(1, MPAD / 128);
        k_mma_gemm<YW><<<grid, 256, GSMEM>>>(yh, yl, wfh, wfl, out, N, DD);
    }
}

// round 7
// speedup vs baseline: 1.7942x; 1.0382x over previous
#include <cuda_runtime.h>
#include <cuda_bf16.h>
#include <cstdint>

// Problem constants (fixed by the dataset)
#define NN    20000
#define MPAD  20096        // 157 * 128
#define EE    320000
#define DD    128
#define HD    256
#define YW    768          // 3 rel * 2 head * 128
#define SCALE 16.0f

// ---------------- scratch (device globals; no allocation) ----------------
__device__ float          g_qt[(size_t)NN * YW];      // fp32 transformed queries [N,768]
__device__ __nv_bfloat16  g_xh[(size_t)MPAD * DD];
__device__ __nv_bfloat16  g_xl[(size_t)MPAD * DD];
__device__ __nv_bfloat16  g_wsch[(size_t)YW * DD];    // Wsc = WK^T WQ blocks, hi/lo [768,128]
__device__ __nv_bfloat16  g_wscl[(size_t)YW * DD];
__device__ __nv_bfloat16  g_wfh[(size_t)DD * YW];     // Wfin = WO x WV blocks, hi/lo [128,768]
__device__ __nv_bfloat16  g_wfl[(size_t)DD * YW];
__device__ __nv_bfloat16  g_yh[(size_t)MPAD * YW];    // weighted-x aggregate hi/lo
__device__ __nv_bfloat16  g_yl[(size_t)MPAD * YW];
__device__ int   g_deg[NN];
__device__ int   g_rowptr[NN + 1];
__device__ int   g_cursor[NN];
__device__ int   g_pack[EE];                          // CSR-ordered src | (rel<<15)

__device__ __forceinline__ uint32_t smem_u32(const void* p) {
    uint32_t a;
    asm("{ .reg .u64 t; cvta.to.shared.u64 t, %1; cvt.u32.u64 %0, t; }" : "=r"(a) : "l"(p));
    return a;
}
__device__ __forceinline__ void ldsm_x4(uint32_t& r0, uint32_t& r1, uint32_t& r2, uint32_t& r3,
                                        uint32_t addr) {
    asm volatile("ldmatrix.sync.aligned.m8n8.x4.shared.b16 {%0,%1,%2,%3}, [%4];"
                 : "=r"(r0), "=r"(r1), "=r"(r2), "=r"(r3) : "r"(addr));
}
__device__ __forceinline__ void mma_bf16(float* d, const uint32_t* a, const uint32_t* b) {
    asm volatile(
        "mma.sync.aligned.m16n8k16.row.col.f32.bf16.bf16.f32 "
        "{%0,%1,%2,%3}, {%4,%5,%6,%7}, {%8,%9}, {%0,%1,%2,%3};"
        : "+f"(d[0]), "+f"(d[1]), "+f"(d[2]), "+f"(d[3])
        : "r"(a[0]), "r"(a[1]), "r"(a[2]), "r"(a[3]), "r"(b[0]), "r"(b[1]));
}
#define CP_ASYNC16(dst, src) \
    asm volatile("cp.async.cg.shared.global [%0], [%1], 16;\n" :: "r"(dst), "l"(src))
#define CP_COMMIT() asm volatile("cp.async.commit_group;\n" ::: "memory")
#define CP_WAIT(n)  asm volatile("cp.async.wait_group %0;\n" :: "n"(n) : "memory")

// ---------------- init ----------------
__global__ void k_init()
{
    int i = blockIdx.x * blockDim.x + threadIdx.x;
    if (i < NN) { g_deg[i] = 0; g_cursor[i] = 0; }
    int padn = (MPAD - NN) * YW;   // 73728
    if (i < padn) {
        g_yh[(size_t)NN * YW + i] = __float2bfloat16(0.0f);
        g_yl[(size_t)NN * YW + i] = __float2bfloat16(0.0f);
    }
}

// ---------------- fp32 -> bf16 hi/lo split ----------------
__global__ void k_split(const float* __restrict__ s, __nv_bfloat16* __restrict__ h,
                        __nv_bfloat16* __restrict__ l, int nreal, int ntot)
{
    int i = blockIdx.x * blockDim.x + threadIdx.x;
    if (i >= ntot) return;
    float x = (i < nreal) ? s[i] : 0.0f;
    __nv_bfloat16 hi = __float2bfloat16(x);
    float lo = x - __bfloat162float(hi);
    h[i] = hi;
    l[i] = __float2bfloat16(lo);
}

// ---------------- Wsc[rh*128+k, d2] = sum_d WK[r, h*128+d, k] * WQ[h*128+d, d2] ----------------
__global__ void k_wsc(const float* __restrict__ WQ, const float* __restrict__ WK)
{
    int rh = blockIdx.x;          // 0..5
    int k  = blockIdx.y;          // 0..127
    int d2 = threadIdx.x;         // 0..127
    int r = rh >> 1, h = rh & 1;
    const float* wk = WK + (size_t)r * HD * DD + (size_t)(h * 128) * DD + k;
    const float* wq = WQ + (size_t)(h * 128) * DD + d2;
    float acc = 0.0f;
    #pragma unroll 8
    for (int d = 0; d < 128; d++)
        acc = fmaf(wk[(size_t)d * DD], wq[(size_t)d * DD], acc);
    size_t idx = (size_t)(rh * 128 + k) * DD + d2;
    __nv_bfloat16 hi = __float2bfloat16(acc);
    g_wsch[idx] = hi;
    g_wscl[idx] = __float2bfloat16(acc - __bfloat162float(hi));
}

// ---------------- Wfin[o,(r*2+h)*128+k] = sum_d WO[o,h*128+d]*WV[r,h*128+d,k]; hi/lo out ----------------
__global__ void k_wfin(const float* __restrict__ WO, const float* __restrict__ WV)
{
    int rh = blockIdx.x;          // 0..5
    int o  = blockIdx.y;          // 0..127
    int k  = threadIdx.x;         // 0..127
    int r = rh >> 1, h = rh & 1;
    const float* wo = WO + o * HD + h * 128;
    const float* wv = WV + ((size_t)(r * HD + h * 128)) * DD + k;
    float acc = 0.0f;
    #pragma unroll 8
    for (int d = 0; d < 128; d++)
        acc = fmaf(wo[d], wv[(size_t)d * DD], acc);
    size_t idx = (size_t)o * YW + rh * 128 + k;
    __nv_bfloat16 hi = __float2bfloat16(acc);
    g_wfh[idx] = hi;
    g_wfl[idx] = __float2bfloat16(acc - __bfloat162float(hi));
}

// ---------------- degree histogram ----------------
__global__ void k_deg(const int* __restrict__ edst, int E)
{
    int e = blockIdx.x * blockDim.x + threadIdx.x;
    if (e < E) atomicAdd(&g_deg[edst[e]], 1);
}

// ---------------- fast scan ----------------
__global__ __launch_bounds__(1024) void k_scan(int n)
{
    const int P = 20;
    __shared__ int wsum[32];
    int tid = threadIdx.x, lane = tid & 31, wid = tid >> 5;
    int base = tid * P;
    int v[P];
    int s = 0;
    #pragma unroll
    for (int i = 0; i < P; i++) {
        int idx = base + i;
        int d = (idx < n) ? g_deg[idx] : 0;
        s += d;
        v[i] = s;
    }
    int x = s;
    #pragma unroll
    for (int off = 1; off < 32; off <<= 1) {
        int t = __shfl_up_sync(0xffffffffu, x, off);
        if (lane >= off) x += t;
    }
    if (lane == 31) wsum[wid] = x;
    __syncthreads();
    if (wid == 0) {
        int y = wsum[lane];
        #pragma unroll
        for (int off = 1; off < 32; off <<= 1) {
            int t = __shfl_up_sync(0xffffffffu, y, off);
            if (lane >= off) y += t;
        }
        wsum[lane] = y;
    }
    __syncthreads();
    int offset = (wid ? wsum[wid - 1] : 0) + x - s;
    if (tid == 0) g_rowptr[0] = 0;
    #pragma unroll
    for (int i = 0; i < P; i++) {
        int idx = base + i;
        if (idx < n) g_rowptr[idx + 1] = offset + v[i];
    }
}

// ---------------- scatter packed src|rel into CSR ----------------
__global__ void k_scatter(const int* __restrict__ esrc, const int* __restrict__ edst,
                          const int* __restrict__ erel, int E)
{
    int e = blockIdx.x * blockDim.x + threadIdx.x;
    if (e >= E) return;
    int dst = edst[e];
    int pos = atomicAdd(&g_cursor[dst], 1);
    g_pack[g_rowptr[dst] + pos] = esrc[e] | (erel[e] << 15);
}

// ---------------- mma.sync GEMM, cp.async double-buffered ----------------
#define SSTR   40
#define TILEB  10240
#define STAGEB (4 * TILEB)
#define GSMEM  (2 * STAGEB)

template <int KD>
__global__ __launch_bounds__(256)
void k_mma_gemm(const __nv_bfloat16* __restrict__ Ah, const __nv_bfloat16* __restrict__ Al,
                const __nv_bfloat16* __restrict__ Bh, const __nv_bfloat16* __restrict__ Bl,
                float* __restrict__ C, int Mreal, int ldc)
{
    extern __shared__ uint8_t dsm[];
    const uint32_t sb = smem_u32(dsm);
    const int tid  = threadIdx.x;
    const int wid  = tid >> 5;
    const int lane = tid & 31;
    const int m0 = blockIdx.y * 128;
    const int j0 = blockIdx.x * 128;
    const int warp_m = (wid & 3) * 32;
    const int warp_n = (wid >> 2) * 64;

    const int ar = lane & 15;
    const int kh = (lane >> 4) << 3;

    float acc[2][8][4];
    #pragma unroll
    for (int i = 0; i < 2; i++)
        #pragma unroll
        for (int j = 0; j < 8; j++)
            #pragma unroll
            for (int q = 0; q < 4; q++) acc[i][j][q] = 0.0f;

    int rowA[2], c8A[2];
    #pragma unroll
    for (int i = 0; i < 2; i++) {
        int v = tid + i * 256;
        rowA[i] = v >> 2;
        c8A[i] = (v & 3) << 3;
    }

    auto prefetch = [&](int kt, int stage) {
        uint32_t base = sb + (uint32_t)stage * STAGEB;
        #pragma unroll
        for (int i = 0; i < 2; i++) {
            int row = rowA[i], c8 = c8A[i];
            uint32_t so = base + (uint32_t)(row * SSTR + c8) * 2;
            size_t ga = (size_t)(m0 + row) * KD + kt + c8;
            size_t gb = (size_t)(j0 + row) * KD + kt + c8;
            CP_ASYNC16(so,             Ah + ga);
            CP_ASYNC16(so + TILEB,     Al + ga);
            CP_ASYNC16(so + 2 * TILEB, Bh + gb);
            CP_ASYNC16(so + 3 * TILEB, Bl + gb);
        }
        CP_COMMIT();
    };

    constexpr int NCH = KD / 32;
    prefetch(0, 0);

    for (int ch = 0; ch < NCH; ch++) {
        if (ch + 1 < NCH) {
            prefetch((ch + 1) * 32, (ch + 1) & 1);
            CP_WAIT(1);
        } else {
            CP_WAIT(0);
        }
        __syncthreads();

        uint32_t base = sb + (uint32_t)(ch & 1) * STAGEB;
        #pragma unroll
        for (int pass = 0; pass < 3; pass++) {
            uint32_t aBase = base + (pass == 2 ? TILEB : 0u);
            uint32_t bBase = base + 2 * TILEB + (pass == 1 ? TILEB : 0u);
            #pragma unroll
            for (int k16 = 0; k16 < 2; k16++) {
                uint32_t kb = (uint32_t)((k16 * 16 + kh) * 2);
                uint32_t a[2][4];
                #pragma unroll
                for (int mi = 0; mi < 2; mi++) {
                    uint32_t ad = aBase + (uint32_t)((warp_m + mi * 16 + ar) * SSTR * 2) + kb;
                    ldsm_x4(a[mi][0], a[mi][1], a[mi][2], a[mi][3], ad);
                }
                uint32_t b[8][2];
                #pragma unroll
                for (int ng = 0; ng < 4; ng++) {
                    uint32_t r0, r1, r2, r3;
                    uint32_t bd = bBase + (uint32_t)((warp_n + ng * 16 + ar) * SSTR * 2) + kb;
                    ldsm_x4(r0, r1, r2, r3, bd);
                    b[ng * 2][0] = r0;     b[ng * 2][1] = r2;
                    b[ng * 2 + 1][0] = r1; b[ng * 2 + 1][1] = r3;
                }
                #pragma unroll
                for (int mi = 0; mi < 2; mi++)
                    #pragma unroll
                    for (int nj = 0; nj < 8; nj++)
                        mma_bf16(acc[mi][nj], a[mi], b[nj]);
            }
        }
        __syncthreads();
    }

    const int rg = lane >> 2;
    const int tg = lane & 3;
    #pragma unroll
    for (int mi = 0; mi < 2; mi++) {
        int r0 = m0 + warp_m + mi * 16 + rg;
        int r1 = r0 + 8;
        #pragma unroll
        for (int nj = 0; nj < 8; nj++) {
            int col = j0 + warp_n + nj * 8 + tg * 2;
            if (r0 < Mreal) {
                float2 v = {acc[mi][nj][0], acc[mi][nj][1]};
                *(float2*)(C + (size_t)r0 * ldc + col) = v;
            }
            if (r1 < Mreal) {
                float2 v = {acc[mi][nj][2], acc[mi][nj][3]};
                *(float2*)(C + (size_t)r1 * ldc + col) = v;
            }
        }
    }
}

// ---------------- fused node kernel ----------------
// qt (transformed queries) resident in registers; per edge only the 512B x row
// is gathered (used for BOTH score and aggregation). 2-edge unroll, pack prefetch.
__global__ __launch_bounds__(256)
void k_node(const float* __restrict__ X, int N)
{
    int warp = (blockIdx.x * blockDim.x + threadIdx.x) >> 5;
    int lane = threadIdx.x & 31;
    if (warp >= N) return;

    const int start = g_rowptr[warp];
    const int end   = g_rowptr[warp + 1];

    // load qt row: 6 combos (r,h) x 4 floats per lane (lane covers dims lane*4..+3)
    float qt[6][4];
    {
        const float* qr = g_qt + (size_t)warp * YW;
        #pragma unroll
        for (int c = 0; c < 6; c++) {
            float4 v = *(const float4*)(qr + c * 128 + lane * 4);
            qt[c][0] = v.x; qt[c][1] = v.y; qt[c][2] = v.z; qt[c][3] = v.w;
        }
    }

    float y[3][2][4];
    #pragma unroll
    for (int r = 0; r < 3; r++)
        #pragma unroll
        for (int h = 0; h < 2; h++)
            #pragma unroll
            for (int i = 0; i < 4; i++) y[r][h][i] = 0.0f;

    float den0 = 0.0f, den1 = 0.0f;

    int j = start;
    int pk0 = (j < end)     ? g_pack[j]     : 0;
    int pk1 = (j + 1 < end) ? g_pack[j + 1] : 0;

    while (j + 1 < end) {
        int s0 = pk0 & 0x7FFF, r0 = pk0 >> 15;
        int s1 = pk1 & 0x7FFF, r1 = pk1 >> 15;
        int nj = j + 2;
        int npk0 = (nj < end)     ? g_pack[nj]     : 0;
        int npk1 = (nj + 1 < end) ? g_pack[nj + 1] : 0;

        float4 xv0 = *(const float4*)(X + (size_t)s0 * DD + lane * 4);
        float4 xv1 = *(const float4*)(X + (size_t)s1 * DD + lane * 4);
        float xa0[4] = {xv0.x, xv0.y, xv0.z, xv0.w};
        float xa1[4] = {xv1.x, xv1.y, xv1.z, xv1.w};

        float p00 = 0.f, p01 = 0.f, p10 = 0.f, p11 = 0.f;
        #pragma unroll
        for (int i = 0; i < 4; i++) {
            p00 = fmaf(qt[r0 * 2][i],     xa0[i], p00);
            p01 = fmaf(qt[r0 * 2 + 1][i], xa0[i], p01);
            p10 = fmaf(qt[r1 * 2][i],     xa1[i], p10);
            p11 = fmaf(qt[r1 * 2 + 1][i], xa1[i], p11);
        }
        #pragma unroll
        for (int off = 16; off >= 1; off >>= 1) {
            p00 += __shfl_xor_sync(0xffffffffu, p00, off);
            p01 += __shfl_xor_sync(0xffffffffu, p01, off);
            p10 += __shfl_xor_sync(0xffffffffu, p10, off);
            p11 += __shfl_xor_sync(0xffffffffu, p11, off);
        }
        float nuA0 = fmaxf(p00 / SCALE, 0.0f); nuA0 = nuA0 * nuA0 + 1e-10f;
        float nuA1 = fmaxf(p01 / SCALE, 0.0f); nuA1 = nuA1 * nuA1 + 1e-10f;
        float nuB0 = fmaxf(p10 / SCALE, 0.0f); nuB0 = nuB0 * nuB0 + 1e-10f;
        float nuB1 = fmaxf(p11 / SCALE, 0.0f); nuB1 = nuB1 * nuB1 + 1e-10f;
        den0 += nuA0 + nuB0;
        den1 += nuA1 + nuB1;

        if (r0 == 0) {
            #pragma unroll
            for (int i = 0; i < 4; i++) { y[0][0][i] += nuA0 * xa0[i]; y[0][1][i] += nuA1 * xa0[i]; }
        } else if (r0 == 1) {
            #pragma unroll
            for (int i = 0; i < 4; i++) { y[1][0][i] += nuA0 * xa0[i]; y[1][1][i] += nuA1 * xa0[i]; }
        } else {
            #pragma unroll
            for (int i = 0; i < 4; i++) { y[2][0][i] += nuA0 * xa0[i]; y[2][1][i] += nuA1 * xa0[i]; }
        }
        if (r1 == 0) {
            #pragma unroll
            for (int i = 0; i < 4; i++) { y[0][0][i] += nuB0 * xa1[i]; y[0][1][i] += nuB1 * xa1[i]; }
        } else if (r1 == 1) {
            #pragma unroll
            for (int i = 0; i < 4; i++) { y[1][0][i] += nuB0 * xa1[i]; y[1][1][i] += nuB1 * xa1[i]; }
        } else {
            #pragma unroll
            for (int i = 0; i < 4; i++) { y[2][0][i] += nuB0 * xa1[i]; y[2][1][i] += nuB1 * xa1[i]; }
        }

        j = nj; pk0 = npk0; pk1 = npk1;
    }

    if (j < end) {
        int s0 = pk0 & 0x7FFF, r0 = pk0 >> 15;
        float4 xv = *(const float4*)(X + (size_t)s0 * DD + lane * 4);
        float xa[4] = {xv.x, xv.y, xv.z, xv.w};
        float p0 = 0.f, p1 = 0.f;
        #pragma unroll
        for (int i = 0; i < 4; i++) {
            p0 = fmaf(qt[r0 * 2][i],     xa[i], p0);
            p1 = fmaf(qt[r0 * 2 + 1][i], xa[i], p1);
        }
        #pragma unroll
        for (int off = 16; off >= 1; off >>= 1) {
            p0 += __shfl_xor_sync(0xffffffffu, p0, off);
            p1 += __shfl_xor_sync(0xffffffffu, p1, off);
        }
        float nu0 = fmaxf(p0 / SCALE, 0.0f); nu0 = nu0 * nu0 + 1e-10f;
        float nu1 = fmaxf(p1 / SCALE, 0.0f); nu1 = nu1 * nu1 + 1e-10f;
        den0 += nu0;
        den1 += nu1;
        if (r0 == 0) {
            #pragma unroll
            for (int i = 0; i < 4; i++) { y[0][0][i] += nu0 * xa[i]; y[0][1][i] += nu1 * xa[i]; }
        } else if (r0 == 1) {
            #pragma unroll
            for (int i = 0; i < 4; i++) { y[1][0][i] += nu0 * xa[i]; y[1][1][i] += nu1 * xa[i]; }
        } else {
            #pragma unroll
            for (int i = 0; i < 4; i++) { y[2][0][i] += nu0 * xa[i]; y[2][1][i] += nu1 * xa[i]; }
        }
    }

    float inv0 = (den0 > 0.0f) ? 1.0f / den0 : 0.0f;
    float inv1 = (den1 > 0.0f) ? 1.0f / den1 : 0.0f;

    #pragma unroll
    for (int r = 0; r < 3; r++)
        #pragma unroll
        for (int h = 0; h < 2; h++) {
            float sc = h ? inv1 : inv0;
            size_t off = (size_t)warp * YW + (r * 2 + h) * 128 + lane * 4;
            #pragma unroll
            for (int i = 0; i < 4; i++) {
                float val = y[r][h][i] * sc;
                __nv_bfloat16 hi = __float2bfloat16(val);
                g_yh[off + i] = hi;
                g_yl[off + i] = __float2bfloat16(val - __bfloat162float(hi));
            }
        }
}

// ---------------- launch ----------------
extern "C" void kernel_launch(void* const* d_in, const int* in_sizes, int n_in,
                              void* d_out, int out_size)
{
    const float* X   = (const float*)d_in[0];
    const float* WQ  = (const float*)d_in[1];
    const float* WK  = (const float*)d_in[2];
    const float* WV  = (const float*)d_in[3];
    const float* WO  = (const float*)d_in[4];
    const int*  esrc = (const int*)d_in[5];
    const int*  edst = (const int*)d_in[6];
    const int*  erel = (const int*)d_in[7];
    float* out = (float*)d_out;

    const int N = NN, E = EE;

    float* qt;
    cudaGetSymbolAddress((void**)&qt, g_qt);
    __nv_bfloat16 *xh, *xl, *wsch, *wscl, *wfh, *wfl, *yh, *yl;
    cudaGetSymbolAddress((void**)&xh,   g_xh);
    cudaGetSymbolAddress((void**)&xl,   g_xl);
    cudaGetSymbolAddress((void**)&wsch, g_wsch);
    cudaGetSymbolAddress((void**)&wscl, g_wscl);
    cudaGetSymbolAddress((void**)&wfh,  g_wfh);
    cudaGetSymbolAddress((void**)&wfl,  g_wfl);
    cudaGetSymbolAddress((void**)&yh,   g_yh);
    cudaGetSymbolAddress((void**)&yl,   g_yl);

    cudaFuncSetAttribute(k_mma_gemm<DD>, cudaFuncAttributeMaxDynamicSharedMemorySize, GSMEM);
    cudaFuncSetAttribute(k_mma_gemm<YW>, cudaFuncAttributeMaxDynamicSharedMemorySize, GSMEM);

    // 1. init + conversions + fused weights
    k_init<<<((MPAD - NN) * YW + 255) / 256, 256>>>();
    k_split<<<(MPAD * DD + 255) / 256, 256>>>(X, xh, xl, N * DD, MPAD * DD);
    {
        dim3 grid(6, 128);
        k_wsc<<<grid, 128>>>(WQ, WK);
        k_wfin<<<grid, 128>>>(WO, WV);
    }

    // 2. CSR build
    k_deg<<<(E + 255) / 256, 256>>>(edst, E);
    k_scan<<<1, 1024>>>(N);
    k_scatter<<<(E + 255) / 256, 256>>>(esrc, edst, erel, E);

    // 3. transformed-query GEMM: [MPAD,128] x [768,128]^T -> g_qt
    {
        dim3 grid(YW / 128, MPAD / 128);
        k_mma_gemm<DD><<<grid, 256, GSMEM>>>(xh, xl, wsch, wscl, qt, N, YW);
    }

    // 4. fused node pass: scores + denom + weighted-x aggregation -> Y hi/lo
    k_node<<<(N + 7) / 8, 256>>>(X, N);

    // 5. final GEMM: [MPAD,768] x [128,768]^T -> out
    {
        dim3 grid(1, MPAD / 128);
        k_mma_gemm<YW><<<grid, 256, GSMEM>>>(yh, yl, wfh, wfl, out, N, DD);
    }
}